// round 7
// baseline (speedup 1.0000x reference)
#include <cuda_runtime.h>
#include <cuda_bf16.h>
#include <math.h>

// ---------------- problem constants ----------------
#define BATCH      16
#define SEQ        2048
#define NTOK       (BATCH*SEQ)          // 32768
#define INPUT_DIM  1024
#define HIDDEN     256
#define D_STATE    32
#define D_INNER    512
#define NHEADS     16
#define HEADDIM    32
#define CONV_DIM   576
#define D_IN_PROJ  1104
#define KCONV      4
#define EPS        1e-5f
#define CHUNK      128
#define NCH        (SEQ/CHUNK)          // 16

// ---------------- scratch (device globals) ----------
__device__ __align__(128) float g_act [NTOK*HIDDEN];      // full precision
__device__ __align__(128) float g_actr[NTOK*HIDDEN];      // tf32-rounded copy
__device__ __align__(128) float g_z   [NTOK*D_IN_PROJ];
__device__ __align__(128) float g_xbc [NTOK*CONV_DIM];
__device__ __align__(128) float g_dt  [NTOK*NHEADS];
__device__ __align__(128) float g_dA  [NTOK*NHEADS];
__device__ __align__(128) float g_y   [NTOK*D_INNER];
__device__ __align__(128) float g_o   [NTOK*HIDDEN];
__device__ __align__(128) float g_cum [NTOK*NHEADS];
__device__ __align__(128) float g_F   [BATCH*NHEADS*NCH*32*32];
__device__ __align__(128) float g_Hin [BATCH*NHEADS*NCH*32*32];
__device__ __align__(128) float g_xr  [NTOK*INPUT_DIM];   // rounded x
__device__ __align__(128) float g_wr  [1351680];          // rounded weights

// offsets into g_wr
#define OFF_IPW  0
#define OFF_INW  262144
#define OFF_OUTW 827392
#define OFF_W1   1089536
#define OFF_W2   1220608

// ---------------- helpers ----------------
__device__ __forceinline__ float blockSum(float v) {
    __shared__ float sh[8];
    __shared__ float total;
    int lane = threadIdx.x & 31, wid = threadIdx.x >> 5;
    #pragma unroll
    for (int o = 16; o > 0; o >>= 1) v += __shfl_xor_sync(0xffffffffu, v, o);
    if (lane == 0) sh[wid] = v;
    __syncthreads();
    if (threadIdx.x == 0) {
        float t = 0.f;
        int nw = (int)(blockDim.x >> 5);
        for (int i = 0; i < nw; i++) t += sh[i];
        total = t;
    }
    __syncthreads();
    return total;
}

__device__ __forceinline__ float siluf(float x) { return x / (1.f + expf(-x)); }

__device__ __forceinline__ unsigned f2tf(float x) {
    unsigned r;
    asm("cvt.rna.tf32.f32 %0, %1;" : "=r"(r) : "f"(x));
    return r;
}
__device__ __forceinline__ float roundtf(float x) {
    return __uint_as_float(f2tf(x));
}

__device__ __forceinline__ void cp_async16(unsigned saddr, const void* gaddr) {
    asm volatile("cp.async.cg.shared.global [%0], [%1], 16;\n"
                 :: "r"(saddr), "l"(gaddr));
}
__device__ __forceinline__ void cp_async16_pred(unsigned saddr, const void* gaddr, int srcsz) {
    asm volatile("cp.async.cg.shared.global [%0], [%1], 16, %2;\n"
                 :: "r"(saddr), "l"(gaddr), "r"(srcsz));
}
__device__ __forceinline__ void cp_commit() {
    asm volatile("cp.async.commit_group;\n");
}
__device__ __forceinline__ void cp_wait0() {
    asm volatile("cp.async.wait_group 0;\n");
}

// ---------------- tf32 pre-round kernel (float4 grid) ----------------------
__global__ void round_kernel(const float* __restrict__ src,
                             float* __restrict__ dst, int n4)
{
    int i = blockIdx.x * blockDim.x + threadIdx.x;
    if (i < n4) {
        float4 v = reinterpret_cast<const float4*>(src)[i];
        v.x = roundtf(v.x); v.y = roundtf(v.y);
        v.z = roundtf(v.z); v.w = roundtf(v.w);
        reinterpret_cast<float4*>(dst)[i] = v;
    }
}

// ---------------- TF32 tensor-core GEMM, cp.async, pre-rounded operands ----
// BM=128 BN=64 BK=16, 256 threads = 8 warps (4x2), warp tile 32x32.
// A and W MUST be tf32-pre-rounded. No cvt in inner loop: mma truncation of
// bits[12:0] is a no-op on pre-rounded values -> numerics identical to the
// round-2 kernel's load-then-cvt stream.
// MODE 0: C full.  MODE 1: gelu then C rounded.  MODE 2: C full + Cr rounded.
template<int MODE>
__global__ void __launch_bounds__(256)
tgemm_kernel(const float* __restrict__ A, const float* __restrict__ W,
             const float* __restrict__ bias, float* __restrict__ C,
             float* __restrict__ Cr,
             int M, int N, int K)
{
    const int ASTR = 20, BSTR = 72;
    __shared__ float As[2][128 * ASTR];
    __shared__ float Bs[2][16  * BSTR];

    int tid = threadIdx.x, lane = tid & 31, warp = tid >> 5;
    int wm = warp >> 1, wn = warp & 1;
    int gid = lane >> 2, tig = lane & 3;
    int row0 = blockIdx.y * 128, col0 = blockIdx.x * 64;

    int akq = tid & 3,  arb = tid >> 2;
    int bnq = tid & 15, bkr = tid >> 4;

    const float* Abase = A + (size_t)row0 * K;
    int bcol = col0 + bnq * 4;
    int bsz  = (bcol < N) ? 16 : 0;

    float acc[2][4][4];
    #pragma unroll
    for (int i = 0; i < 2; i++)
        #pragma unroll
        for (int j = 0; j < 4; j++)
            #pragma unroll
            for (int q = 0; q < 4; q++) acc[i][j][q] = 0.f;

    unsigned sa0 = (unsigned)__cvta_generic_to_shared(&As[0][arb * ASTR + akq * 4]);
    unsigned sa1 = (unsigned)__cvta_generic_to_shared(&As[0][(arb + 64) * ASTR + akq * 4]);
    unsigned sb  = (unsigned)__cvta_generic_to_shared(&Bs[0][bkr * BSTR + bnq * 4]);
    const unsigned stageA = 128 * ASTR * 4;
    const unsigned stageB = 16  * BSTR * 4;

    cp_async16(sa0, &Abase[(size_t)arb * K + akq * 4]);
    cp_async16(sa1, &Abase[(size_t)(arb + 64) * K + akq * 4]);
    cp_async16_pred(sb, &W[(size_t)bkr * N + bcol], bsz);
    cp_commit();

    int nkt = K >> 4;
    for (int t = 0; t < nkt; t++) {
        cp_wait0();
        __syncthreads();

        int st = t & 1;
        if (t + 1 < nkt) {
            int kt = (t + 1) << 4;
            int ns = (t + 1) & 1;
            cp_async16(sa0 + ns * stageA, &Abase[(size_t)arb * K + kt + akq * 4]);
            cp_async16(sa1 + ns * stageA, &Abase[(size_t)(arb + 64) * K + kt + akq * 4]);
            cp_async16_pred(sb + ns * stageB, &W[(size_t)(kt + bkr) * N + bcol], bsz);
            cp_commit();
        }

        #pragma unroll
        for (int kc = 0; kc < 2; kc++) {
            unsigned af[2][4], bf[4][2];
            #pragma unroll
            for (int im = 0; im < 2; im++) {
                const float* base = &As[st][(wm*32 + im*16 + gid)*ASTR + kc*8 + tig];
                af[im][0] = __float_as_uint(base[0]);
                af[im][1] = __float_as_uint(base[8*ASTR]);
                af[im][2] = __float_as_uint(base[4]);
                af[im][3] = __float_as_uint(base[8*ASTR + 4]);
            }
            #pragma unroll
            for (int jn = 0; jn < 4; jn++) {
                int cb = wn*32 + jn*8 + gid;
                bf[jn][0] = __float_as_uint(Bs[st][(kc*8 + tig    )*BSTR + cb]);
                bf[jn][1] = __float_as_uint(Bs[st][(kc*8 + tig + 4)*BSTR + cb]);
            }
            #pragma unroll
            for (int im = 0; im < 2; im++)
                #pragma unroll
                for (int jn = 0; jn < 4; jn++) {
                    asm volatile(
                        "mma.sync.aligned.m16n8k8.row.col.f32.tf32.tf32.f32 "
                        "{%0,%1,%2,%3}, {%4,%5,%6,%7}, {%8,%9}, {%0,%1,%2,%3};"
                        : "+f"(acc[im][jn][0]), "+f"(acc[im][jn][1]),
                          "+f"(acc[im][jn][2]), "+f"(acc[im][jn][3])
                        : "r"(af[im][0]), "r"(af[im][1]),
                          "r"(af[im][2]), "r"(af[im][3]),
                          "r"(bf[jn][0]), "r"(bf[jn][1]));
                }
        }
    }

    #pragma unroll
    for (int im = 0; im < 2; im++) {
        #pragma unroll
        for (int jn = 0; jn < 4; jn++) {
            int col = col0 + wn*32 + jn*8 + tig*2;
            if (col >= N) continue;
            float b0 = bias[col], b1 = bias[col + 1];
            int r0 = row0 + wm*32 + im*16 + gid;
            float v0 = acc[im][jn][0] + b0;
            float v1 = acc[im][jn][1] + b1;
            float v2 = acc[im][jn][2] + b0;
            float v3 = acc[im][jn][3] + b1;
            if (MODE == 1) {
                v0 = 0.5f*v0*(1.f + erff(v0*0.70710678118654752f));
                v1 = 0.5f*v1*(1.f + erff(v1*0.70710678118654752f));
                v2 = 0.5f*v2*(1.f + erff(v2*0.70710678118654752f));
                v3 = 0.5f*v3*(1.f + erff(v3*0.70710678118654752f));
            }
            if (MODE == 0 || MODE == 2) {
                *reinterpret_cast<float2*>(&C[(size_t)r0 * N + col]) = make_float2(v0, v1);
                *reinterpret_cast<float2*>(&C[(size_t)(r0+8) * N + col]) = make_float2(v2, v3);
            }
            if (MODE == 1) {
                *reinterpret_cast<float2*>(&C[(size_t)r0 * N + col]) =
                    make_float2(roundtf(v0), roundtf(v1));
                *reinterpret_cast<float2*>(&C[(size_t)(r0+8) * N + col]) =
                    make_float2(roundtf(v2), roundtf(v3));
            }
            if (MODE == 2) {
                *reinterpret_cast<float2*>(&Cr[(size_t)r0 * N + col]) =
                    make_float2(roundtf(v0), roundtf(v1));
                *reinterpret_cast<float2*>(&Cr[(size_t)(r0+8) * N + col]) =
                    make_float2(roundtf(v2), roundtf(v3));
            }
        }
    }
}

// ---------------- conv (causal depthwise K=4) + silu + dt/dA ---------------
__global__ void conv_kernel(const float* __restrict__ z,
                            const float* __restrict__ convw,
                            const float* __restrict__ convb,
                            const float* __restrict__ dtb,
                            const float* __restrict__ Alog,
                            float* __restrict__ xbc,
                            float* __restrict__ dtO,
                            float* __restrict__ dAO)
{
    int tok = blockIdx.x;
    int b = tok >> 11, l = tok & 2047;
    for (int c = threadIdx.x; c < CONV_DIM + NHEADS; c += blockDim.x) {
        if (c < CONV_DIM) {
            float acc = convb[c];
            #pragma unroll
            for (int i = 0; i < KCONV; i++) {
                int ll = l - (KCONV - 1) + i;
                if (ll >= 0)
                    acc = fmaf(convw[c*KCONV + i],
                               z[(size_t)(b*SEQ + ll) * D_IN_PROJ + D_INNER + c], acc);
            }
            xbc[(size_t)tok * CONV_DIM + c] = siluf(acc);
        } else {
            int hh = c - CONV_DIM;
            float v = z[(size_t)tok * D_IN_PROJ + 2*D_INNER + 2*D_STATE + hh] + dtb[hh];
            float sp = (v > 20.f) ? v : log1pf(expf(v));
            dtO[tok*NHEADS + hh] = sp;
            dAO[tok*NHEADS + hh] = expf(-expf(Alog[hh]) * sp);
        }
    }
}

// ---------------- chunked selective scan: pass 1 (local scans) -------------
#define TT 32
__global__ void __launch_bounds__(128)
scan_local_kernel(const float* __restrict__ xbc, const float* __restrict__ dt,
                  const float* __restrict__ dA, const float* __restrict__ Dv,
                  float* __restrict__ y, float* __restrict__ cumO,
                  float* __restrict__ F)
{
    int hI = blockIdx.x;
    int b  = blockIdx.y;
    int ch = blockIdx.z;
    int lane = threadIdx.x & 31;
    int w    = threadIdx.x >> 5;
    float Dh = Dv[hI];

    float hs[8];
    #pragma unroll
    for (int i = 0; i < 8; i++) hs[i] = 0.f;
    float cum = 1.f;

    __shared__ float sB[TT][32];
    __shared__ float sC[TT][32];
    __shared__ float sdtx[TT][32];
    __shared__ float sxh[TT][32];
    __shared__ float sdA[TT];
    __shared__ float scum[TT];
    __shared__ float ypart[4][TT][32];

    int tchunk0 = b * SEQ + ch * CHUNK;

    for (int tile = 0; tile < CHUNK / TT; tile++) {
        int t0 = tchunk0 + tile * TT;
        for (int j = threadIdx.x; j < TT * 32; j += 128) {
            int tl = j >> 5, c = j & 31;
            int tok = t0 + tl;
            const float* row = xbc + (size_t)tok * CONV_DIM;
            sB[tl][c] = row[D_INNER + c];
            sC[tl][c] = row[D_INNER + D_STATE + c];
            float xv = row[hI * HEADDIM + c];
            sxh[tl][c]  = xv;
            sdtx[tl][c] = dt[tok * NHEADS + hI] * xv;
        }
        if (threadIdx.x < TT)
            sdA[threadIdx.x] = dA[(t0 + threadIdx.x) * NHEADS + hI];
        __syncthreads();

        for (int tl = 0; tl < TT; tl++) {
            float a  = sdA[tl];
            cum *= a;
            float dx = sdtx[tl][lane];
            float acc = 0.f;
            #pragma unroll
            for (int i = 0; i < 8; i++) {
                int n = w * 8 + i;
                hs[i] = fmaf(hs[i], a, dx * sB[tl][n]);
                acc   = fmaf(hs[i], sC[tl][n], acc);
            }
            ypart[w][tl][lane] = acc;
            if (threadIdx.x == 0) scum[tl] = cum;
        }
        __syncthreads();

        for (int j = threadIdx.x; j < TT * 32; j += 128) {
            int tl = j >> 5, p = j & 31;
            int tok = t0 + tl;
            float yv = ypart[0][tl][p] + ypart[1][tl][p] +
                       ypart[2][tl][p] + ypart[3][tl][p] + Dh * sxh[tl][p];
            y[(size_t)tok * D_INNER + hI * HEADDIM + p] = yv;
            if (p == 0) cumO[tok * NHEADS + hI] = scum[tl];
        }
        __syncthreads();
    }

    size_t fbase = (size_t)(((b * NHEADS + hI) * NCH + ch)) * 1024;
    #pragma unroll
    for (int i = 0; i < 8; i++) {
        int n = w * 8 + i;
        F[fbase + n * 32 + lane] = hs[i];
    }
}

// ---------------- pass 2: combine chunk states -----------------------------
__global__ void __launch_bounds__(256)
scan_combine_kernel(const float* __restrict__ F, const float* __restrict__ cum,
                    float* __restrict__ Hin)
{
    int hI = blockIdx.x, b = blockIdx.y;
    size_t base = (size_t)((b * NHEADS + hI) * NCH) * 1024;
    int off = threadIdx.x * 4;
    float4 hr = make_float4(0.f, 0.f, 0.f, 0.f);
    for (int c = 0; c < NCH; c++) {
        *reinterpret_cast<float4*>(&Hin[base + (size_t)c * 1024 + off]) = hr;
        float P = cum[(size_t)(b * SEQ + c * CHUNK + CHUNK - 1) * NHEADS + hI];
        float4 f = *reinterpret_cast<const float4*>(&F[base + (size_t)c * 1024 + off]);
        hr.x = fmaf(hr.x, P, f.x);
        hr.y = fmaf(hr.y, P, f.y);
        hr.z = fmaf(hr.z, P, f.z);
        hr.w = fmaf(hr.w, P, f.w);
    }
}

// ---------------- pass 3: apply chunk-initial-state correction -------------
__global__ void __launch_bounds__(128)
scan_fix_kernel(const float* __restrict__ xbc, const float* __restrict__ cum,
                const float* __restrict__ Hin, float* __restrict__ y)
{
    int hI = blockIdx.x, b = blockIdx.y, ch = blockIdx.z;
    if (ch == 0) return;
    int lane = threadIdx.x & 31, w = threadIdx.x >> 5;

    __shared__ float sh[32][32];
    size_t base = (size_t)(((b * NHEADS + hI) * NCH + ch)) * 1024;
    for (int j = threadIdx.x; j < 1024; j += 128)
        sh[j >> 5][j & 31] = Hin[base + j];
    __syncthreads();

    int t0 = b * SEQ + ch * CHUNK + w * 32;
    for (int tt = 0; tt < 32; tt++) {
        int tok = t0 + tt;
        float cv = xbc[(size_t)tok * CONV_DIM + D_INNER + D_STATE + lane];
        float pt = cum[tok * NHEADS + hI];
        float a0 = 0.f, a1 = 0.f;
        #pragma unroll
        for (int n = 0; n < 32; n += 2) {
            a0 = fmaf(__shfl_sync(0xffffffffu, cv, n),     sh[n][lane],     a0);
            a1 = fmaf(__shfl_sync(0xffffffffu, cv, n + 1), sh[n + 1][lane], a1);
        }
        y[(size_t)tok * D_INNER + hI * HEADDIM + lane] += pt * (a0 + a1);
    }
}

// ---------------- gated RMSNorm (output tf32-rounded: feeds out-proj GEMM) --
__global__ void __launch_bounds__(256)
gatednorm_kernel(float* __restrict__ y, const float* __restrict__ zx,
                 const float* __restrict__ nw)
{
    int tok = blockIdx.x;
    float v[2]; float ss = 0.f;
    #pragma unroll
    for (int r = 0; r < 2; r++) {
        int c = threadIdx.x + r * 256;
        float zv = zx[(size_t)tok * D_IN_PROJ + c];
        float yv = y[(size_t)tok * D_INNER + c];
        v[r] = yv * siluf(zv);
        ss += v[r] * v[r];
    }
    ss = blockSum(ss);
    float scale = rsqrtf(ss / (float)D_INNER + EPS);
    #pragma unroll
    for (int r = 0; r < 2; r++) {
        int c = threadIdx.x + r * 256;
        y[(size_t)tok * D_INNER + c] = roundtf(v[r] * scale * nw[c]);
    }
}

// ---------------- residual + RMSNorm (dual write full + rounded) ------------
__global__ void __launch_bounds__(256)
resnorm_kernel(const float* __restrict__ o, float* __restrict__ act,
               float* __restrict__ actr, const float* __restrict__ wgt)
{
    int tok = blockIdx.x, c = threadIdx.x;
    float v = o[(size_t)tok * HIDDEN + c] + act[(size_t)tok * HIDDEN + c];
    float ss = blockSum(v * v);
    float r = v * rsqrtf(ss / (float)HIDDEN + EPS) * wgt[c];
    act [(size_t)tok * HIDDEN + c] = r;
    actr[(size_t)tok * HIDDEN + c] = roundtf(r);
}

// ---------------- LayerNorm (DOROUND=1 -> output feeds a GEMM) --------------
template<int DOROUND>
__global__ void __launch_bounds__(256)
layernorm_kernel(const float* __restrict__ in, const float* __restrict__ w,
                 const float* __restrict__ bsl, float* __restrict__ out)
{
    int tok = blockIdx.x, c = threadIdx.x;
    float v = in[(size_t)tok * HIDDEN + c];
    float s  = blockSum(v);
    float s2 = blockSum(v * v);
    float m = s / (float)HIDDEN;
    float var = s2 / (float)HIDDEN - m * m;
    float r = (v - m) * rsqrtf(var + EPS) * w[c] + bsl[c];
    out[(size_t)tok * HIDDEN + c] = DOROUND ? roundtf(r) : r;
}

// ---------------- launch ----------------------------------------------------
extern "C" void kernel_launch(void* const* d_in, const int* in_sizes, int n_in,
                              void* d_out, int out_size)
{
    const float* x      = (const float*)d_in[0];
    const float* ip_w   = (const float*)d_in[1];
    const float* ip_b   = (const float*)d_in[2];
    const float* m_inw  = (const float*)d_in[3];
    const float* m_inb  = (const float*)d_in[4];
    const float* m_convw= (const float*)d_in[5];
    const float* m_convb= (const float*)d_in[6];
    const float* m_dtb  = (const float*)d_in[7];
    const float* m_Alog = (const float*)d_in[8];
    const float* m_D    = (const float*)d_in[9];
    const float* m_nw   = (const float*)d_in[10];
    const float* m_outw = (const float*)d_in[11];
    const float* m_outb = (const float*)d_in[12];
    const float* rms_w  = (const float*)d_in[13];
    const float* ln1_w  = (const float*)d_in[14];
    const float* ln1_b  = (const float*)d_in[15];
    const float* w1     = (const float*)d_in[16];
    const float* b1     = (const float*)d_in[17];
    const float* w2     = (const float*)d_in[18];
    const float* b2     = (const float*)d_in[19];
    const float* ln2_w  = (const float*)d_in[20];
    const float* ln2_b  = (const float*)d_in[21];
    float* out = (float*)d_out;

    float *act, *actr, *z, *xbc, *dt, *dA, *y, *o, *cum, *F, *Hin, *xr, *wr;
    cudaGetSymbolAddress((void**)&act,  g_act);
    cudaGetSymbolAddress((void**)&actr, g_actr);
    cudaGetSymbolAddress((void**)&z,    g_z);
    cudaGetSymbolAddress((void**)&xbc,  g_xbc);
    cudaGetSymbolAddress((void**)&dt,   g_dt);
    cudaGetSymbolAddress((void**)&dA,   g_dA);
    cudaGetSymbolAddress((void**)&y,    g_y);
    cudaGetSymbolAddress((void**)&o,    g_o);
    cudaGetSymbolAddress((void**)&cum,  g_cum);
    cudaGetSymbolAddress((void**)&F,    g_F);
    cudaGetSymbolAddress((void**)&Hin,  g_Hin);
    cudaGetSymbolAddress((void**)&xr,   g_xr);
    cudaGetSymbolAddress((void**)&wr,   g_wr);

    // ---- pre-round x and all GEMM weights to the tf32 grid ----
    {
        int n4;
        n4 = NTOK*INPUT_DIM/4;
        round_kernel<<<(n4+255)/256, 256>>>(x, xr, n4);
        n4 = INPUT_DIM*HIDDEN/4;
        round_kernel<<<(n4+255)/256, 256>>>(ip_w, wr + OFF_IPW, n4);
        n4 = 2*HIDDEN*D_IN_PROJ/4;
        round_kernel<<<(n4+255)/256, 256>>>(m_inw, wr + OFF_INW, n4);
        n4 = 2*D_INNER*HIDDEN/4;
        round_kernel<<<(n4+255)/256, 256>>>(m_outw, wr + OFF_OUTW, n4);
        n4 = HIDDEN*2*HIDDEN/4;
        round_kernel<<<(n4+255)/256, 256>>>(w1, wr + OFF_W1, n4);
        n4 = 2*HIDDEN*HIDDEN/4;
        round_kernel<<<(n4+255)/256, 256>>>(w2, wr + OFF_W2, n4);
    }

    const int MB = NTOK / 128;

    // input projection: act(full)+actr(rounded) = xr @ ipw_r + ip_b
    tgemm_kernel<2><<<dim3(HIDDEN/64, MB), 256>>>(xr, wr + OFF_IPW, ip_b,
                                                  act, actr, NTOK, HIDDEN, INPUT_DIM);

    for (int i = 0; i < 2; i++) {
        tgemm_kernel<0><<<dim3((D_IN_PROJ + 63) / 64, MB), 256>>>(
            actr, wr + OFF_INW + (size_t)i * HIDDEN * D_IN_PROJ, m_inb + i * D_IN_PROJ,
            z, (float*)nullptr, NTOK, D_IN_PROJ, HIDDEN);
        conv_kernel<<<NTOK, 256>>>(z, m_convw + (size_t)i * CONV_DIM * KCONV,
                                   m_convb + i * CONV_DIM, m_dtb + i * NHEADS,
                                   m_Alog + i * NHEADS, xbc, dt, dA);
        scan_local_kernel<<<dim3(NHEADS, BATCH, NCH), 128>>>(
            xbc, dt, dA, m_D + i * NHEADS, y, cum, F);
        scan_combine_kernel<<<dim3(NHEADS, BATCH), 256>>>(F, cum, Hin);
        scan_fix_kernel<<<dim3(NHEADS, BATCH, NCH), 128>>>(xbc, cum, Hin, y);
        gatednorm_kernel<<<NTOK, 256>>>(y, z, m_nw + i * D_INNER);   // y rounded
        tgemm_kernel<0><<<dim3(HIDDEN/64, MB), 256>>>(
            y, wr + OFF_OUTW + (size_t)i * D_INNER * HIDDEN, m_outb + i * HIDDEN,
            o, (float*)nullptr, NTOK, HIDDEN, D_INNER);
        resnorm_kernel<<<NTOK, 256>>>(o, act, actr, rms_w + i * HIDDEN);
    }

    layernorm_kernel<1><<<NTOK, 256>>>(act, ln1_w, ln1_b, o);        // o rounded
    tgemm_kernel<1><<<dim3((2*HIDDEN)/64, MB), 256>>>(o, wr + OFF_W1, b1,
                                                      y, (float*)nullptr,
                                                      NTOK, 2*HIDDEN, HIDDEN); // gelu+round
    tgemm_kernel<0><<<dim3(HIDDEN/64, MB), 256>>>(y, wr + OFF_W2, b2,
                                                  o, (float*)nullptr,
                                                  NTOK, HIDDEN, 2*HIDDEN);
    layernorm_kernel<0><<<NTOK, 256>>>(o, ln2_w, ln2_b, out);
}

// round 9
// speedup vs baseline: 1.0427x; 1.0427x over previous
#include <cuda_runtime.h>
#include <cuda_bf16.h>
#include <math.h>

// ---------------- problem constants ----------------
#define BATCH      16
#define SEQ        2048
#define NTOK       (BATCH*SEQ)          // 32768
#define INPUT_DIM  1024
#define HIDDEN     256
#define D_STATE    32
#define D_INNER    512
#define NHEADS     16
#define HEADDIM    32
#define CONV_DIM   576
#define D_IN_PROJ  1104
#define KCONV      4
#define EPS        1e-5f
#define CHUNK      128
#define NCH        (SEQ/CHUNK)          // 16

// ---------------- scratch (device globals) ----------
__device__ __align__(128) float g_act [NTOK*HIDDEN];
__device__ __align__(128) float g_z   [NTOK*D_IN_PROJ];
__device__ __align__(128) float g_xbc [NTOK*CONV_DIM];
__device__ __align__(128) float g_dt  [NTOK*NHEADS];
__device__ __align__(128) float g_dA  [NTOK*NHEADS];
__device__ __align__(128) float g_y   [NTOK*D_INNER];
__device__ __align__(128) float g_o   [NTOK*HIDDEN];
__device__ __align__(128) float g_cum [NTOK*NHEADS];
__device__ __align__(128) float g_F   [BATCH*NHEADS*NCH*32*32];
__device__ __align__(128) float g_Hin [BATCH*NHEADS*NCH*32*32];

// ---------------- helpers ----------------
__device__ __forceinline__ float blockSum(float v) {
    __shared__ float sh[8];
    __shared__ float total;
    int lane = threadIdx.x & 31, wid = threadIdx.x >> 5;
    #pragma unroll
    for (int o = 16; o > 0; o >>= 1) v += __shfl_xor_sync(0xffffffffu, v, o);
    if (lane == 0) sh[wid] = v;
    __syncthreads();
    if (threadIdx.x == 0) {
        float t = 0.f;
        int nw = (int)(blockDim.x >> 5);
        for (int i = 0; i < nw; i++) t += sh[i];
        total = t;
    }
    __syncthreads();
    return total;
}

__device__ __forceinline__ float siluf(float x) { return x / (1.f + expf(-x)); }

__device__ __forceinline__ unsigned f2tf(float x) {
    unsigned r;
    asm("cvt.rna.tf32.f32 %0, %1;" : "=r"(r) : "f"(x));
    return r;
}

__device__ __forceinline__ void cp_async16(unsigned saddr, const void* gaddr) {
    asm volatile("cp.async.cg.shared.global [%0], [%1], 16;\n"
                 :: "r"(saddr), "l"(gaddr));
}
__device__ __forceinline__ void cp_async16_pred(unsigned saddr, const void* gaddr, int srcsz) {
    asm volatile("cp.async.cg.shared.global [%0], [%1], 16, %2;\n"
                 :: "r"(saddr), "l"(gaddr), "r"(srcsz));
}
__device__ __forceinline__ void cp_commit() { asm volatile("cp.async.commit_group;\n"); }
__device__ __forceinline__ void cp_wait1()  { asm volatile("cp.async.wait_group 1;\n"); }

// ---------------- TF32 tensor-core GEMM -------------------------------------
// Block 128x128x16, 128 threads = 4 warps (2x2), warp tile 64x64, 3-stage
// cp.async pipeline. tf32 conversion at fragment load (cvt.rna) -> per-output
// value stream + mma k-order identical to the round-2/6 kernels.
// MODE 0: C = A@W + bias.  MODE 1: gelu epilogue.
#define ASTR 20
#define BSTR 136
#define A_STG (128*ASTR)               // 2560 floats
#define B_STG (16*BSTR)                // 2176 floats
#define B_BASE (3*A_STG)               // 7680
#define SM_FLOATS (3*A_STG + 3*B_STG)  // 14208 floats = 56832 B

template<int MODE>
__global__ void __launch_bounds__(128)
tgemm_kernel(const float* __restrict__ A, const float* __restrict__ W,
             const float* __restrict__ bias, float* __restrict__ C,
             int M, int N, int K)
{
    extern __shared__ float sm[];
    int tid = threadIdx.x, lane = tid & 31, warp = tid >> 5;
    int wm = warp >> 1, wn = warp & 1;       // 2x2 warps, 64x64 each
    int gid = lane >> 2, tig = lane & 3;
    int row0 = blockIdx.y * 128, col0 = blockIdx.x * 128;

    int akq = tid & 3,  arb = tid >> 2;      // A: rows arb+p*32, float4 col akq
    int bnq = tid & 31, bkr = tid >> 5;      // B: rows bkr+p*4,  float4 col bnq

    const float* Abase = A + (size_t)row0 * K;
    int bcol = col0 + bnq * 4;
    int bsz  = (bcol < N) ? 16 : 0;

    float acc[4][8][4];
    #pragma unroll
    for (int i = 0; i < 4; i++)
        #pragma unroll
        for (int j = 0; j < 8; j++)
            #pragma unroll
            for (int q = 0; q < 4; q++) acc[i][j][q] = 0.f;

    unsigned smbase = (unsigned)__cvta_generic_to_shared(sm);
    int nkt = K >> 4;

    // prologue: stages 0,1
    #pragma unroll
    for (int s = 0; s < 2; s++) {
        if (s < nkt) {
            int kt = s << 4;
            #pragma unroll
            for (int p = 0; p < 4; p++)
                cp_async16(smbase + (s*A_STG + (arb + p*32)*ASTR + akq*4)*4,
                           &Abase[(size_t)(arb + p*32) * K + kt + akq*4]);
            #pragma unroll
            for (int p = 0; p < 4; p++)
                cp_async16_pred(smbase + (B_BASE + s*B_STG + (bkr + p*4)*BSTR + bnq*4)*4,
                                &W[(size_t)(kt + bkr + p*4) * N + bcol], bsz);
        }
        cp_commit();
    }

    for (int t = 0; t < nkt; t++) {
        cp_wait1();
        __syncthreads();

        // prefetch stage t+2
        {
            int tn = t + 2;
            if (tn < nkt) {
                int s = tn % 3;
                int kt = tn << 4;
                #pragma unroll
                for (int p = 0; p < 4; p++)
                    cp_async16(smbase + (s*A_STG + (arb + p*32)*ASTR + akq*4)*4,
                               &Abase[(size_t)(arb + p*32) * K + kt + akq*4]);
                #pragma unroll
                for (int p = 0; p < 4; p++)
                    cp_async16_pred(smbase + (B_BASE + s*B_STG + (bkr + p*4)*BSTR + bnq*4)*4,
                                    &W[(size_t)(kt + bkr + p*4) * N + bcol], bsz);
            }
            cp_commit();
        }

        const float* As = sm + (t % 3) * A_STG;
        const float* Bs = sm + B_BASE + (t % 3) * B_STG;

        #pragma unroll
        for (int kc = 0; kc < 2; kc++) {
            unsigned af[4][4], bf[8][2];
            #pragma unroll
            for (int im = 0; im < 4; im++) {
                const float* base = &As[(wm*64 + im*16 + gid)*ASTR + kc*8 + tig];
                af[im][0] = f2tf(base[0]);
                af[im][1] = f2tf(base[8*ASTR]);
                af[im][2] = f2tf(base[4]);
                af[im][3] = f2tf(base[8*ASTR + 4]);
            }
            #pragma unroll
            for (int jn = 0; jn < 8; jn++) {
                int cb = wn*64 + jn*8 + gid;
                bf[jn][0] = f2tf(Bs[(kc*8 + tig    )*BSTR + cb]);
                bf[jn][1] = f2tf(Bs[(kc*8 + tig + 4)*BSTR + cb]);
            }
            #pragma unroll
            for (int im = 0; im < 4; im++)
                #pragma unroll
                for (int jn = 0; jn < 8; jn++) {
                    asm volatile(
                        "mma.sync.aligned.m16n8k8.row.col.f32.tf32.tf32.f32 "
                        "{%0,%1,%2,%3}, {%4,%5,%6,%7}, {%8,%9}, {%0,%1,%2,%3};"
                        : "+f"(acc[im][jn][0]), "+f"(acc[im][jn][1]),
                          "+f"(acc[im][jn][2]), "+f"(acc[im][jn][3])
                        : "r"(af[im][0]), "r"(af[im][1]),
                          "r"(af[im][2]), "r"(af[im][3]),
                          "r"(bf[jn][0]), "r"(bf[jn][1]));
                }
        }
    }

    // epilogue
    #pragma unroll
    for (int im = 0; im < 4; im++) {
        #pragma unroll
        for (int jn = 0; jn < 8; jn++) {
            int col = col0 + wn*64 + jn*8 + tig*2;
            if (col >= N) continue;
            float b0 = bias[col], b1 = bias[col + 1];
            int r0 = row0 + wm*64 + im*16 + gid;
            float v0 = acc[im][jn][0] + b0;
            float v1 = acc[im][jn][1] + b1;
            float v2 = acc[im][jn][2] + b0;
            float v3 = acc[im][jn][3] + b1;
            if (MODE == 1) {
                v0 = 0.5f*v0*(1.f + erff(v0*0.70710678118654752f));
                v1 = 0.5f*v1*(1.f + erff(v1*0.70710678118654752f));
                v2 = 0.5f*v2*(1.f + erff(v2*0.70710678118654752f));
                v3 = 0.5f*v3*(1.f + erff(v3*0.70710678118654752f));
            }
            *reinterpret_cast<float2*>(&C[(size_t)r0 * N + col]) = make_float2(v0, v1);
            *reinterpret_cast<float2*>(&C[(size_t)(r0+8) * N + col]) = make_float2(v2, v3);
        }
    }
}

// ---------------- conv (causal depthwise K=4) + silu + dt/dA ---------------
__global__ void conv_kernel(const float* __restrict__ z,
                            const float* __restrict__ convw,
                            const float* __restrict__ convb,
                            const float* __restrict__ dtb,
                            const float* __restrict__ Alog,
                            float* __restrict__ xbc,
                            float* __restrict__ dtO,
                            float* __restrict__ dAO)
{
    int tok = blockIdx.x;
    int b = tok >> 11, l = tok & 2047;
    for (int c = threadIdx.x; c < CONV_DIM + NHEADS; c += blockDim.x) {
        if (c < CONV_DIM) {
            float acc = convb[c];
            #pragma unroll
            for (int i = 0; i < KCONV; i++) {
                int ll = l - (KCONV - 1) + i;
                if (ll >= 0)
                    acc = fmaf(convw[c*KCONV + i],
                               z[(size_t)(b*SEQ + ll) * D_IN_PROJ + D_INNER + c], acc);
            }
            xbc[(size_t)tok * CONV_DIM + c] = siluf(acc);
        } else {
            int hh = c - CONV_DIM;
            float v = z[(size_t)tok * D_IN_PROJ + 2*D_INNER + 2*D_STATE + hh] + dtb[hh];
            float sp = (v > 20.f) ? v : log1pf(expf(v));
            dtO[tok*NHEADS + hh] = sp;
            dAO[tok*NHEADS + hh] = expf(-expf(Alog[hh]) * sp);
        }
    }
}

// ---------------- chunked selective scan: pass 1 (local scans) -------------
#define TT 32
__global__ void __launch_bounds__(128)
scan_local_kernel(const float* __restrict__ xbc, const float* __restrict__ dt,
                  const float* __restrict__ dA, const float* __restrict__ Dv,
                  float* __restrict__ y, float* __restrict__ cumO,
                  float* __restrict__ F)
{
    int hI = blockIdx.x;
    int b  = blockIdx.y;
    int ch = blockIdx.z;
    int lane = threadIdx.x & 31;
    int w    = threadIdx.x >> 5;
    float Dh = Dv[hI];

    float hs[8];
    #pragma unroll
    for (int i = 0; i < 8; i++) hs[i] = 0.f;
    float cum = 1.f;

    __shared__ float sB[TT][32];
    __shared__ float sC[TT][32];
    __shared__ float sdtx[TT][32];
    __shared__ float sxh[TT][32];
    __shared__ float sdA[TT];
    __shared__ float scum[TT];
    __shared__ float ypart[4][TT][32];

    int tchunk0 = b * SEQ + ch * CHUNK;

    for (int tile = 0; tile < CHUNK / TT; tile++) {
        int t0 = tchunk0 + tile * TT;
        for (int j = threadIdx.x; j < TT * 32; j += 128) {
            int tl = j >> 5, c = j & 31;
            int tok = t0 + tl;
            const float* row = xbc + (size_t)tok * CONV_DIM;
            sB[tl][c] = row[D_INNER + c];
            sC[tl][c] = row[D_INNER + D_STATE + c];
            float xv = row[hI * HEADDIM + c];
            sxh[tl][c]  = xv;
            sdtx[tl][c] = dt[tok * NHEADS + hI] * xv;
        }
        if (threadIdx.x < TT)
            sdA[threadIdx.x] = dA[(t0 + threadIdx.x) * NHEADS + hI];
        __syncthreads();

        for (int tl = 0; tl < TT; tl++) {
            float a  = sdA[tl];
            cum *= a;
            float dx = sdtx[tl][lane];
            float acc = 0.f;
            #pragma unroll
            for (int i = 0; i < 8; i++) {
                int n = w * 8 + i;
                hs[i] = fmaf(hs[i], a, dx * sB[tl][n]);
                acc   = fmaf(hs[i], sC[tl][n], acc);
            }
            ypart[w][tl][lane] = acc;
            if (threadIdx.x == 0) scum[tl] = cum;
        }
        __syncthreads();

        for (int j = threadIdx.x; j < TT * 32; j += 128) {
            int tl = j >> 5, p = j & 31;
            int tok = t0 + tl;
            float yv = ypart[0][tl][p] + ypart[1][tl][p] +
                       ypart[2][tl][p] + ypart[3][tl][p] + Dh * sxh[tl][p];
            y[(size_t)tok * D_INNER + hI * HEADDIM + p] = yv;
            if (p == 0) cumO[tok * NHEADS + hI] = scum[tl];
        }
        __syncthreads();
    }

    size_t fbase = (size_t)(((b * NHEADS + hI) * NCH + ch)) * 1024;
    #pragma unroll
    for (int i = 0; i < 8; i++) {
        int n = w * 8 + i;
        F[fbase + n * 32 + lane] = hs[i];
    }
}

// ---------------- pass 2: combine chunk states -----------------------------
__global__ void __launch_bounds__(256)
scan_combine_kernel(const float* __restrict__ F, const float* __restrict__ cum,
                    float* __restrict__ Hin)
{
    int hI = blockIdx.x, b = blockIdx.y;
    size_t base = (size_t)((b * NHEADS + hI) * NCH) * 1024;
    int off = threadIdx.x * 4;
    float4 hr = make_float4(0.f, 0.f, 0.f, 0.f);
    for (int c = 0; c < NCH; c++) {
        *reinterpret_cast<float4*>(&Hin[base + (size_t)c * 1024 + off]) = hr;
        float P = cum[(size_t)(b * SEQ + c * CHUNK + CHUNK - 1) * NHEADS + hI];
        float4 f = *reinterpret_cast<const float4*>(&F[base + (size_t)c * 1024 + off]);
        hr.x = fmaf(hr.x, P, f.x);
        hr.y = fmaf(hr.y, P, f.y);
        hr.z = fmaf(hr.z, P, f.z);
        hr.w = fmaf(hr.w, P, f.w);
    }
}

// ---------------- pass 3: apply chunk-initial-state correction -------------
__global__ void __launch_bounds__(128)
scan_fix_kernel(const float* __restrict__ xbc, const float* __restrict__ cum,
                const float* __restrict__ Hin, float* __restrict__ y)
{
    int hI = blockIdx.x, b = blockIdx.y, ch = blockIdx.z;
    if (ch == 0) return;
    int lane = threadIdx.x & 31, w = threadIdx.x >> 5;

    __shared__ float sh[32][32];
    size_t base = (size_t)(((b * NHEADS + hI) * NCH + ch)) * 1024;
    for (int j = threadIdx.x; j < 1024; j += 128)
        sh[j >> 5][j & 31] = Hin[base + j];
    __syncthreads();

    int t0 = b * SEQ + ch * CHUNK + w * 32;
    for (int tt = 0; tt < 32; tt++) {
        int tok = t0 + tt;
        float cv = xbc[(size_t)tok * CONV_DIM + D_INNER + D_STATE + lane];
        float pt = cum[tok * NHEADS + hI];
        float a0 = 0.f, a1 = 0.f;
        #pragma unroll
        for (int n = 0; n < 32; n += 2) {
            a0 = fmaf(__shfl_sync(0xffffffffu, cv, n),     sh[n][lane],     a0);
            a1 = fmaf(__shfl_sync(0xffffffffu, cv, n + 1), sh[n + 1][lane], a1);
        }
        y[(size_t)tok * D_INNER + hI * HEADDIM + lane] += pt * (a0 + a1);
    }
}

// ---------------- gated RMSNorm --------------------------------------------
__global__ void __launch_bounds__(256)
gatednorm_kernel(float* __restrict__ y, const float* __restrict__ zx,
                 const float* __restrict__ nw)
{
    int tok = blockIdx.x;
    float v[2]; float ss = 0.f;
    #pragma unroll
    for (int r = 0; r < 2; r++) {
        int c = threadIdx.x + r * 256;
        float zv = zx[(size_t)tok * D_IN_PROJ + c];
        float yv = y[(size_t)tok * D_INNER + c];
        v[r] = yv * siluf(zv);
        ss += v[r] * v[r];
    }
    ss = blockSum(ss);
    float scale = rsqrtf(ss / (float)D_INNER + EPS);
    #pragma unroll
    for (int r = 0; r < 2; r++) {
        int c = threadIdx.x + r * 256;
        y[(size_t)tok * D_INNER + c] = v[r] * scale * nw[c];
    }
}

// ---------------- residual + RMSNorm ---------------------------------------
__global__ void __launch_bounds__(256)
resnorm_kernel(const float* __restrict__ o, float* __restrict__ act,
               const float* __restrict__ wgt)
{
    int tok = blockIdx.x, c = threadIdx.x;
    float v = o[(size_t)tok * HIDDEN + c] + act[(size_t)tok * HIDDEN + c];
    float ss = blockSum(v * v);
    act[(size_t)tok * HIDDEN + c] = v * rsqrtf(ss / (float)HIDDEN + EPS) * wgt[c];
}

// ---------------- LayerNorm ------------------------------------------------
__global__ void __launch_bounds__(256)
layernorm_kernel(const float* __restrict__ in, const float* __restrict__ w,
                 const float* __restrict__ bsl, float* __restrict__ out)
{
    int tok = blockIdx.x, c = threadIdx.x;
    float v = in[(size_t)tok * HIDDEN + c];
    float s  = blockSum(v);
    float s2 = blockSum(v * v);
    float m = s / (float)HIDDEN;
    float var = s2 / (float)HIDDEN - m * m;
    out[(size_t)tok * HIDDEN + c] = (v - m) * rsqrtf(var + EPS) * w[c] + bsl[c];
}

// ---------------- launch ----------------------------------------------------
extern "C" void kernel_launch(void* const* d_in, const int* in_sizes, int n_in,
                              void* d_out, int out_size)
{
    const float* x      = (const float*)d_in[0];
    const float* ip_w   = (const float*)d_in[1];
    const float* ip_b   = (const float*)d_in[2];
    const float* m_inw  = (const float*)d_in[3];
    const float* m_inb  = (const float*)d_in[4];
    const float* m_convw= (const float*)d_in[5];
    const float* m_convb= (const float*)d_in[6];
    const float* m_dtb  = (const float*)d_in[7];
    const float* m_Alog = (const float*)d_in[8];
    const float* m_D    = (const float*)d_in[9];
    const float* m_nw   = (const float*)d_in[10];
    const float* m_outw = (const float*)d_in[11];
    const float* m_outb = (const float*)d_in[12];
    const float* rms_w  = (const float*)d_in[13];
    const float* ln1_w  = (const float*)d_in[14];
    const float* ln1_b  = (const float*)d_in[15];
    const float* w1     = (const float*)d_in[16];
    const float* b1     = (const float*)d_in[17];
    const float* w2     = (const float*)d_in[18];
    const float* b2     = (const float*)d_in[19];
    const float* ln2_w  = (const float*)d_in[20];
    const float* ln2_b  = (const float*)d_in[21];
    float* out = (float*)d_out;

    float *act, *z, *xbc, *dt, *dA, *y, *o, *cum, *F, *Hin;
    cudaGetSymbolAddress((void**)&act, g_act);
    cudaGetSymbolAddress((void**)&z,   g_z);
    cudaGetSymbolAddress((void**)&xbc, g_xbc);
    cudaGetSymbolAddress((void**)&dt,  g_dt);
    cudaGetSymbolAddress((void**)&dA,  g_dA);
    cudaGetSymbolAddress((void**)&y,   g_y);
    cudaGetSymbolAddress((void**)&o,   g_o);
    cudaGetSymbolAddress((void**)&cum, g_cum);
    cudaGetSymbolAddress((void**)&F,   g_F);
    cudaGetSymbolAddress((void**)&Hin, g_Hin);

    const int SMB = SM_FLOATS * 4;   // 56832 bytes dynamic smem
    cudaFuncSetAttribute(tgemm_kernel<0>, cudaFuncAttributeMaxDynamicSharedMemorySize, SMB);
    cudaFuncSetAttribute(tgemm_kernel<1>, cudaFuncAttributeMaxDynamicSharedMemorySize, SMB);

    const int MB = NTOK / 128;   // 256 row-blocks

    tgemm_kernel<0><<<dim3((HIDDEN+127)/128, MB), 128, SMB>>>(
        x, ip_w, ip_b, act, NTOK, HIDDEN, INPUT_DIM);

    for (int i = 0; i < 2; i++) {
        tgemm_kernel<0><<<dim3((D_IN_PROJ + 127) / 128, MB), 128, SMB>>>(
            act, m_inw + (size_t)i * HIDDEN * D_IN_PROJ, m_inb + i * D_IN_PROJ,
            z, NTOK, D_IN_PROJ, HIDDEN);
        conv_kernel<<<NTOK, 256>>>(z, m_convw + (size_t)i * CONV_DIM * KCONV,
                                   m_convb + i * CONV_DIM, m_dtb + i * NHEADS,
                                   m_Alog + i * NHEADS, xbc, dt, dA);
        scan_local_kernel<<<dim3(NHEADS, BATCH, NCH), 128>>>(
            xbc, dt, dA, m_D + i * NHEADS, y, cum, F);
        scan_combine_kernel<<<dim3(NHEADS, BATCH), 256>>>(F, cum, Hin);
        scan_fix_kernel<<<dim3(NHEADS, BATCH, NCH), 128>>>(xbc, cum, Hin, y);
        gatednorm_kernel<<<NTOK, 256>>>(y, z, m_nw + i * D_INNER);
        tgemm_kernel<0><<<dim3((HIDDEN+127)/128, MB), 128, SMB>>>(
            y, m_outw + (size_t)i * D_INNER * HIDDEN, m_outb + i * HIDDEN,
            o, NTOK, HIDDEN, D_INNER);
        resnorm_kernel<<<NTOK, 256>>>(o, act, rms_w + i * HIDDEN);
    }

    layernorm_kernel<<<NTOK, 256>>>(act, ln1_w, ln1_b, o);
    tgemm_kernel<1><<<dim3((2*HIDDEN + 127)/128, MB), 128, SMB>>>(
        o, w1, b1, y, NTOK, 2*HIDDEN, HIDDEN);
    tgemm_kernel<0><<<dim3((HIDDEN+127)/128, MB), 128, SMB>>>(
        y, w2, b2, o, NTOK, HIDDEN, 2*HIDDEN);
    layernorm_kernel<<<NTOK, 256>>>(o, ln2_w, ln2_b, out);
}